// round 3
// baseline (speedup 1.0000x reference)
#include <cuda_runtime.h>
#include <cuda_bf16.h>
#include <cstdint>

// ---------------- Problem dims ----------------
#define B_SZ   256
#define T_LEN  1024
#define I_DIM  64
#define H_DIM  256
#define KX     320            // 256 (h) + 64 (x_t) unified K
#define NBG    16             // batch groups
#define NGG    8              // gate-group CTAs per batch group
#define WS     128            // weight tile row stride (floats)
#define HS     32             // duplicated-h stride (floats)
#define GP     132            // gate-spill stride

#define SMEM_FLOATS (KX*WS + KX*HS + 16*GP + 512)
#define SMEM_BYTES  (SMEM_FLOATS * 4)

// ---------------- Static device scratch ----------------
__device__ float        g_xT[T_LEN][NBG][I_DIM][16];   // x transposed, k-major
__device__ float        g_HT[2][NBG][H_DIM][16];       // ping-pong hidden, k-major
__device__ unsigned int g_cnt[NBG * 32];               // per-group arrival counters

// ---------------- helpers ----------------
__device__ __forceinline__ unsigned long long ffma2(unsigned long long a,
                                                    unsigned long long b,
                                                    unsigned long long c) {
  unsigned long long d;
  asm("fma.rn.f32x2 %0, %1, %2, %3;" : "=l"(d) : "l"(a), "l"(b), "l"(c));
  return d;
}
__device__ __forceinline__ unsigned int ld_acq(const unsigned int* p) {
  unsigned int v;
  asm volatile("ld.acquire.gpu.global.u32 %0, [%1];" : "=r"(v) : "l"(p) : "memory");
  return v;
}
__device__ __forceinline__ void red_rel(unsigned int* p) {
  asm volatile("red.release.gpu.global.add.u32 [%0], 1;" :: "l"(p) : "memory");
}
__device__ __forceinline__ float fsig(float x) {
  x = fminf(fmaxf(x, -15.0f), 15.0f);
  return __fdividef(1.0f, 1.0f + __expf(-x));
}
__device__ __forceinline__ float ftanh(float x) {
  x = fminf(fmaxf(x, -15.0f), 15.0f);
  float e = __expf(-2.0f * x);
  return __fdividef(1.0f - e, 1.0f + e);
}

// ---------------- Kernels ----------------
__global__ void reset_kernel() {
  if (threadIdx.x < NBG * 32) g_cnt[threadIdx.x] = 0u;
}

// x [B][T][I] -> g_xT [T][bg][c][bl]
__global__ void xt_kernel(const float* __restrict__ x) {
  long long i = (long long)blockIdx.x * 256 + threadIdx.x;
  int c = (int)(i & 63);
  int t = (int)((i >> 6) & 1023);
  int b = (int)(i >> 16);
  g_xT[t][b >> 4][c][b & 15] = x[i];
}

__global__ void __launch_bounds__(256, 1) lstm_kernel(
    const float* __restrict__ W_ih,
    const float* __restrict__ W_hh,
    const float* __restrict__ b_ih,
    const float* __restrict__ b_hh) {
  extern __shared__ float smem[];
  float* Wsm = smem;               // [KX][WS] weight slice, k-major
  float* hsm = Wsm + KX * WS;      // [KX][HS] duplicated [h; x_t], k-major
  float* gsm = hsm + KX * HS;      // [16][GP] gate pre-activations
  float* csm = gsm + 16 * GP;      // [16][32] cell state

  const int tid = threadIdx.x;
  const int bg  = blockIdx.x >> 3;
  const int gg  = blockIdx.x & 7;
  const int c0  = gg * 32;

  // ---- one-time: weight slice -> smem, gate rows regrouped ----
  for (int i = tid; i < 128 * H_DIM; i += 256) {   // W_hh part (k < 256)
    int r = i >> 8, k = i & 255;
    int gr = (r >> 5) * H_DIM + c0 + (r & 31);
    Wsm[k * WS + r] = W_hh[gr * H_DIM + k];
  }
  for (int i = tid; i < 128 * I_DIM; i += 256) {   // W_ih part (k >= 256)
    int r = i >> 6, k = i & 63;
    int gr = (r >> 5) * H_DIM + c0 + (r & 31);
    Wsm[(H_DIM + k) * WS + r] = W_ih[gr * I_DIM + k];
  }
  for (int i = tid; i < KX * HS; i += 256) hsm[i] = 0.0f;
  csm[tid] = 0.0f;
  csm[tid + 256] = 0.0f;

  // K-loop mapping: thread = 4 rows x 2 batch
  const int rg = tid >> 3;              // row group: rows rg*4..rg*4+3
  const int bp = tid & 7;               // batch pair: b = 2bp, 2bp+1
  const float* wp = Wsm + rg * 4;
  const float* hp = hsm + bp * 4;       // (b0,b0,b1,b1) duplicated pairs

  // epilogue mapping: 1 col x 2 batch
  const int ecol = tid & 31;
  const int ebq  = tid >> 5;
  float bias[4];
#pragma unroll
  for (int g = 0; g < 4; g++) {
    int gr = g * H_DIM + c0 + ecol;
    bias[g] = b_ih[gr] + b_hh[gr];
  }

  // fill mapping: float4 index tid -> col, batch-quad
  const int fc = tid >> 2;
  const int fb = (tid & 3) * 4;

  unsigned int* flag = &g_cnt[bg * 32];

  // preload x(0)
  float4 xr = __ldcg((const float4*)&g_xT[0][bg][0][0] + tid);

  __syncthreads();

  for (int t = 0; t < T_LEN; t++) {
    // ---- STS duplicated x_t into hsm x-part (k >= 256) ----
    {
      float4* d = (float4*)(hsm + (H_DIM + fc) * HS + 2 * fb);
      d[0] = make_float4(xr.x, xr.x, xr.y, xr.y);
      d[1] = make_float4(xr.z, xr.z, xr.w, xr.w);
    }
    __syncthreads();

    // ---- wait for h_t to be published ----
    if (t) {
      if (tid == 0) {
        unsigned int target = (unsigned int)(NGG * t);
        while (ld_acq(flag) < target) { }
      }
      __syncthreads();
    }

    // ---- issue h_t loads, hide under x-part compute ----
    float4 h0, h1, h2, h3;
    if (t) {
      const float4* src = (const float4*)&g_HT[t & 1][bg][0][0];
      h0 = __ldcg(src + tid);
      h1 = __ldcg(src + tid + 256);
      h2 = __ldcg(src + tid + 512);
      h3 = __ldcg(src + tid + 768);
    }

    unsigned long long acc00 = 0, acc01 = 0, acc10 = 0, acc11 = 0;
#pragma unroll 8
    for (int k = H_DIM; k < KX; k++) {        // phase A: x rows
      ulonglong2 w2 = *(const ulonglong2*)(wp + k * WS);
      ulonglong2 hd = *(const ulonglong2*)(hp + k * HS);
      acc00 = ffma2(w2.x, hd.x, acc00);
      acc01 = ffma2(w2.y, hd.x, acc01);
      acc10 = ffma2(w2.x, hd.y, acc10);
      acc11 = ffma2(w2.y, hd.y, acc11);
    }

    // ---- STS duplicated h_t into hsm h-part (k < 256) ----
    if (t) {
      float4* d0 = (float4*)(hsm + (fc +   0) * HS + 2 * fb);
      d0[0] = make_float4(h0.x, h0.x, h0.y, h0.y);
      d0[1] = make_float4(h0.z, h0.z, h0.w, h0.w);
      float4* d1 = (float4*)(hsm + (fc +  64) * HS + 2 * fb);
      d1[0] = make_float4(h1.x, h1.x, h1.y, h1.y);
      d1[1] = make_float4(h1.z, h1.z, h1.w, h1.w);
      float4* d2 = (float4*)(hsm + (fc + 128) * HS + 2 * fb);
      d2[0] = make_float4(h2.x, h2.x, h2.y, h2.y);
      d2[1] = make_float4(h2.z, h2.z, h2.w, h2.w);
      float4* d3 = (float4*)(hsm + (fc + 192) * HS + 2 * fb);
      d3[0] = make_float4(h3.x, h3.x, h3.y, h3.y);
      d3[1] = make_float4(h3.z, h3.z, h3.w, h3.w);
    }
    __syncthreads();

#pragma unroll 8
    for (int k = 0; k < H_DIM; k++) {         // phase B: h rows
      ulonglong2 w2 = *(const ulonglong2*)(wp + k * WS);
      ulonglong2 hd = *(const ulonglong2*)(hp + k * HS);
      acc00 = ffma2(w2.x, hd.x, acc00);
      acc01 = ffma2(w2.y, hd.x, acc01);
      acc10 = ffma2(w2.x, hd.y, acc10);
      acc11 = ffma2(w2.y, hd.y, acc11);
    }

    // ---- spill gates ----
    {
      int b = bp * 2;
      ulonglong2 s0; s0.x = acc00; s0.y = acc01;
      ulonglong2 s1; s1.x = acc10; s1.y = acc11;
      *(ulonglong2*)(gsm + b * GP + rg * 4)       = s0;
      *(ulonglong2*)(gsm + (b + 1) * GP + rg * 4) = s1;
    }
    __syncthreads();

    // ---- prefetch x(t+1) under epilogue ----
    if (t + 1 < T_LEN)
      xr = __ldcg((const float4*)&g_xT[t + 1][bg][0][0] + tid);

    // ---- epilogue: activations + c/h update (CTA-local) ----
#pragma unroll
    for (int u = 0; u < 2; u++) {
      int b = ebq + u * 8;
      float gi = gsm[b * GP +  0 + ecol] + bias[0];
      float gf = gsm[b * GP + 32 + ecol] + bias[1];
      float gc = gsm[b * GP + 64 + ecol] + bias[2];
      float go = gsm[b * GP + 96 + ecol] + bias[3];
      float iv = fsig(gi), fv = fsig(gf), cv = ftanh(gc), ov = fsig(go);
      float cnew = fv * csm[b * 32 + ecol] + iv * cv;
      csm[b * 32 + ecol] = cnew;
      float h = ov * ftanh(cnew);
      __stcg(&g_HT[(t + 1) & 1][bg][c0 + ecol][b], h);
    }
    __syncthreads();
    if (tid == 0) red_rel(flag);
  }
}

// out[bg*16+b] = h_last[.,b] . fc_w + fc_b   (h_last in g_HT[0])
__global__ void fc_kernel(const float* __restrict__ fc_w,
                          const float* __restrict__ fc_b,
                          float* __restrict__ out) {
  __shared__ float part[256];
  int bg = blockIdx.x;
  int cq = threadIdx.x >> 4;
  int b  = threadIdx.x & 15;
  float s = 0.0f;
#pragma unroll
  for (int j = 0; j < 16; j++) {
    int col = cq * 16 + j;
    s += g_HT[0][bg][col][b] * fc_w[col];
  }
  part[threadIdx.x] = s;
  __syncthreads();
  if (threadIdx.x < 16) {
    float acc = 0.0f;
#pragma unroll
    for (int q = 0; q < 16; q++) acc += part[q * 16 + threadIdx.x];
    out[bg * 16 + threadIdx.x] = acc + fc_b[0];
  }
}

// ---------------- Launch ----------------
extern "C" void kernel_launch(void* const* d_in, const int* in_sizes, int n_in,
                              void* d_out, int out_size) {
  const float* x    = (const float*)d_in[0];
  const float* W_ih = (const float*)d_in[1];
  const float* W_hh = (const float*)d_in[2];
  const float* b_ih = (const float*)d_in[3];
  const float* b_hh = (const float*)d_in[4];
  const float* fc_w = (const float*)d_in[5];
  const float* fc_b = (const float*)d_in[6];
  float* out = (float*)d_out;

  static bool attr_set = false;
  if (!attr_set) {
    cudaFuncSetAttribute(lstm_kernel,
                         cudaFuncAttributeMaxDynamicSharedMemorySize, SMEM_BYTES);
    attr_set = true;
  }

  reset_kernel<<<1, 512>>>();
  xt_kernel<<<(B_SZ * T_LEN * I_DIM) / 256, 256>>>(x);
  lstm_kernel<<<NBG * NGG, 256, SMEM_BYTES>>>(W_ih, W_hh, b_ih, b_hh);
  fc_kernel<<<NBG, 256>>>(fc_w, fc_b, out);
}

// round 5
// speedup vs baseline: 3.0563x; 3.0563x over previous
#include <cuda_runtime.h>
#include <cuda_bf16.h>
#include <cstdint>

// ---------------- dims ----------------
#define NBG    16       // batch groups (16 batch each)
#define NGG    8        // gate-slice CTAs per group (32 h-cols each)
#define BB     16       // batch per group (MMA M)
#define T_LEN  1024
#define H_DIM  256
#define I_DIM  64
#define NKS    20       // k-steps of 16 (K = 320)
#define KHALF  10       // k-steps per k-half warp

// ---------------- smem layout (bytes) ----------------
// W fragment regions: [hi_t01, hi_t23, lo_t01, lo_t23], each [gate(4)][ks(20)][lane(32)][16B]
#define WREG     40960
#define W_OFF    0
#define HX_OFF   (4 * WREG)            // 163840: hx hi [20][32][16B] then lo (+10240)
#define SP_OFF   (HX_OFF + 20480)      // 184320: 2 k-half spills, [b(16)][136 floats]
#define SP_HALF  8704
#define HSTG_OFF (SP_OFF + 2 * SP_HALF)  // 201728: h frag staging [ls(2)][plane(2)][512B]
#define SMEM_TOTAL (HSTG_OFF + 2048)     // 203776

// ---------------- static scratch ----------------
// B-operand (hx) staging in fragment layout: [t][bg]{hi 10240 | lo 10240}
__device__ char          g_B[(size_t)(T_LEN + 1) * NBG * 20480];
__device__ float         g_Hf[256][256];   // final hidden fp32
__device__ unsigned int  g_cnt[NBG * 32];

// ---------------- helpers ----------------
__device__ __forceinline__ unsigned int ld_acq(const unsigned int* p) {
  unsigned int v;
  asm volatile("ld.acquire.gpu.global.u32 %0, [%1];" : "=r"(v) : "l"(p) : "memory");
  return v;
}
__device__ __forceinline__ void red_rel(unsigned int* p) {
  asm volatile("red.release.gpu.global.add.u32 [%0], 1;" :: "l"(p) : "memory");
}
__device__ __forceinline__ float fsig(float x) {
  x = fminf(fmaxf(x, -15.0f), 15.0f);
  return __fdividef(1.0f, 1.0f + __expf(-x));
}
__device__ __forceinline__ float ftanh(float x) {
  x = fminf(fmaxf(x, -15.0f), 15.0f);
  float e = __expf(-2.0f * x);
  return __fdividef(1.0f - e, 1.0f + e);
}
__device__ __forceinline__ void mma16816(float* d, const uint4& a,
                                         uint32_t b0, uint32_t b1) {
  asm volatile(
      "mma.sync.aligned.m16n8k16.row.col.f32.bf16.bf16.f32 "
      "{%0,%1,%2,%3}, {%4,%5,%6,%7}, {%8,%9}, {%0,%1,%2,%3};"
      : "+f"(d[0]), "+f"(d[1]), "+f"(d[2]), "+f"(d[3])
      : "r"(a.x), "r"(a.y), "r"(a.z), "r"(a.w), "r"(b0), "r"(b1));
}

// fragment address helper (B-operand / A-operand of hx): element (batch b, k_in)
// lane = (b&7)*4 + u ; byte = reg*4 + half*2 ; reg = (b>=8) + 2*(k_in>=8)
__device__ __forceinline__ int hx_frag_off(int b, int k_in) {
  int u    = (k_in & 7) >> 1;
  int half = k_in & 1;
  int reg  = ((b >> 3) & 1) + ((k_in >> 3) & 1) * 2;
  return ((b & 7) * 4 + u) * 16 + reg * 4 + half * 2;
}

// ---------------- prep kernels ----------------
__global__ void reset_kernel() {
  if (threadIdx.x < NBG * 32) g_cnt[threadIdx.x] = 0u;
}

// stage x (hi/lo) into g_B k-steps 16..19 for all t
__global__ void xprep_kernel(const float* __restrict__ x) {
  int id  = blockIdx.x * 256 + threadIdx.x;      // 16,777,216
  int i   = id & 63;
  int t   = (id >> 6) & 1023;
  int bgl = id >> 16;
  float v = x[(size_t)bgl * (T_LEN * I_DIM) + t * 64 + i];
  __nv_bfloat16 hi = __float2bfloat16(v);
  __nv_bfloat16 lo = __float2bfloat16(v - __bfloat162float(hi));
  int bg = bgl >> 4, b = bgl & 15;
  int ks = 16 + (i >> 4);
  int off = ks * 512 + hx_frag_off(b, i & 15);
  char* base = g_B + ((size_t)t * NBG + bg) * 20480;
  *(__nv_bfloat16*)(base + off)         = hi;
  *(__nv_bfloat16*)(base + 10240 + off) = lo;
}

// ---------------- main persistent kernel ----------------
__global__ void __launch_bounds__(256, 1) lstm_kernel(
    const float* __restrict__ W_ih, const float* __restrict__ W_hh,
    const float* __restrict__ b_ih, const float* __restrict__ b_hh) {
  extern __shared__ char smem[];
  const int tid  = threadIdx.x;
  const int w    = tid >> 5;
  const int lane = tid & 31;
  const int bg   = blockIdx.x >> 3;
  const int gg   = blockIdx.x & 7;
  const int c0   = gg * 32;

  // ---- one-time: W slice -> smem fragment-major (hi/lo, tiles split) ----
  for (int idx = tid; idx < 128 * 320; idx += 256) {
    int r = idx / 320, k = idx - r * 320;
    int gate = r >> 5, hc = r & 31;
    int gr = gate * H_DIM + c0 + hc;
    float v = (k < H_DIM) ? W_hh[gr * H_DIM + k] : W_ih[gr * I_DIM + (k - 256)];
    __nv_bfloat16 hi = __float2bfloat16(v);
    __nv_bfloat16 lo = __float2bfloat16(v - __bfloat162float(hi));
    int ks = k >> 4, k_in = k & 15;
    int u = (k_in & 7) >> 1, half = k_in & 1, rh = (k_in >> 3) & 1;
    int j = (r >> 3) & 3;                 // n8 tile within the gate's 32 rows
    int off = gate * 10240 + ks * 512 + ((r & 7) * 4 + u) * 16 +
              (j & 1) * 8 + rh * 4 + half * 2;
    int regidx = j >> 1;                  // tiles {0,1} vs {2,3}
    *(__nv_bfloat16*)(smem + W_OFF + regidx * WREG + off)       = hi;
    *(__nv_bfloat16*)(smem + W_OFF + (2 + regidx) * WREG + off) = lo;
  }

  // ---- MMA mapping: ns = gate slice, kh = k-half ----
  const int ns = w & 3;
  const int kh = w >> 2;
  const char* pA_hi = smem + HX_OFF + kh * KHALF * 512 + lane * 16;
  const char* pA_lo = pA_hi + 10240;
  const char* pB    = smem + W_OFF + ns * 10240 + kh * KHALF * 512 + lane * 16;

  // ---- epilogue mapping: (eb, ehc) and (eb+8, ehc) ----
  const int ehc = tid & 31;
  const int eb  = tid >> 5;
  float bias[4];
#pragma unroll
  for (int g = 0; g < 4; g++)
    bias[g] = b_ih[g * H_DIM + c0 + ehc] + b_hh[g * H_DIM + c0 + ehc];
  float cs[2] = {0.f, 0.f};

  unsigned int* flag = &g_cnt[bg * 32];
  __syncthreads();

  for (int t = 0; t < T_LEN; t++) {
    // ---- wait for h(t) from all 8 CTAs of this group ----
    if (t) {
      if (tid == 0) {
        unsigned int target = (unsigned int)(NGG * t);
        while (ld_acq(flag) < target) { }
      }
      __syncthreads();
    }

    // ---- copy-in hx fragments (20KB, layout-identical) ----
    {
      const char* src = g_B + ((size_t)t * NBG + bg) * 20480;
#pragma unroll
      for (int i = 0; i < 5; i++) {
        uint4 v = __ldcg((const uint4*)(src + (tid + i * 256) * 16));
        *(uint4*)(smem + HX_OFF + (tid + i * 256) * 16) = v;
      }
    }
    __syncthreads();

    // ---- MMA mainloop: 10 ksteps x (aH,aL)x(bH,bL tiles), 3 products ----
    float acc[16];
#pragma unroll
    for (int i = 0; i < 16; i++) acc[i] = 0.f;
#pragma unroll
    for (int ks = 0; ks < KHALF; ks++) {
      uint4 aH  = *(const uint4*)(pA_hi + ks * 512);
      uint4 aL  = *(const uint4*)(pA_lo + ks * 512);
      uint4 bh0 = *(const uint4*)(pB + ks * 512);
      uint4 bh1 = *(const uint4*)(pB + WREG + ks * 512);
      uint4 bl0 = *(const uint4*)(pB + 2 * WREG + ks * 512);
      uint4 bl1 = *(const uint4*)(pB + 3 * WREG + ks * 512);
      // tile 0
      mma16816(acc + 0,  aH, bh0.x, bh0.y);
      mma16816(acc + 0,  aH, bl0.x, bl0.y);
      mma16816(acc + 0,  aL, bh0.x, bh0.y);
      // tile 1
      mma16816(acc + 4,  aH, bh0.z, bh0.w);
      mma16816(acc + 4,  aH, bl0.z, bl0.w);
      mma16816(acc + 4,  aL, bh0.z, bh0.w);
      // tile 2
      mma16816(acc + 8,  aH, bh1.x, bh1.y);
      mma16816(acc + 8,  aH, bl1.x, bl1.y);
      mma16816(acc + 8,  aL, bh1.x, bh1.y);
      // tile 3
      mma16816(acc + 12, aH, bh1.z, bh1.w);
      mma16816(acc + 12, aH, bl1.z, bl1.w);
      mma16816(acc + 12, aL, bh1.z, bh1.w);
    }

    // ---- spill partial D to smem: [kh][b][136] ----
    {
      int u = lane & 3, g = lane >> 2;
      float* sp = (float*)(smem + SP_OFF + kh * SP_HALF);
#pragma unroll
      for (int j = 0; j < 4; j++) {
        int r = ns * 32 + j * 8 + 2 * u;
        *(float2*)(sp + g * 136 + r)       = make_float2(acc[4 * j], acc[4 * j + 1]);
        *(float2*)(sp + (g + 8) * 136 + r) = make_float2(acc[4 * j + 2], acc[4 * j + 3]);
      }
    }
    __syncthreads();

    // ---- epilogue: combine k-halves, activations, c/h, stage h frags ----
    {
      const float* s0 = (const float*)(smem + SP_OFF);
      const float* s1 = (const float*)(smem + SP_OFF + SP_HALF);
      int ls = ehc >> 4, k_in = ehc & 15;
#pragma unroll
      for (int uu = 0; uu < 2; uu++) {
        int b = eb + uu * 8;
        float gi = s0[b * 136 +   0 + ehc] + s1[b * 136 +   0 + ehc] + bias[0];
        float gf = s0[b * 136 +  32 + ehc] + s1[b * 136 +  32 + ehc] + bias[1];
        float gc = s0[b * 136 +  64 + ehc] + s1[b * 136 +  64 + ehc] + bias[2];
        float go = s0[b * 136 +  96 + ehc] + s1[b * 136 +  96 + ehc] + bias[3];
        float iv = fsig(gi), fv = fsig(gf), cv = ftanh(gc), ov = fsig(go);
        float cn = fv * cs[uu] + iv * cv;
        cs[uu] = cn;
        float hv = ov * ftanh(cn);
        __nv_bfloat16 hi = __float2bfloat16(hv);
        __nv_bfloat16 lo = __float2bfloat16(hv - __bfloat162float(hi));
        int off = hx_frag_off(b, k_in);
        *(__nv_bfloat16*)(smem + HSTG_OFF + ls * 1024 + off)       = hi;
        *(__nv_bfloat16*)(smem + HSTG_OFF + ls * 1024 + 512 + off) = lo;
        if (t == T_LEN - 1) g_Hf[bg * BB + b][c0 + ehc] = hv;
      }
    }
    __syncthreads();

    // ---- publish this CTA's 2 ksteps of h(t+1) fragments (2KB) ----
    {
      int c = tid >> 6;            // chunk: ls*2 + plane
      int of = (tid & 63) * 8;
      int ls = c >> 1, pl = c & 1;
      unsigned long long v =
          *(const unsigned long long*)(smem + HSTG_OFF + c * 512 + of);
      char* dst = g_B + ((size_t)(t + 1) * NBG + bg) * 20480 + pl * 10240 +
                  (2 * gg + ls) * 512 + of;
      __stcg((unsigned long long*)dst, v);
    }
    __syncthreads();
    if (tid == 0) red_rel(flag);
  }
}

// ---------------- fc ----------------
__global__ void fc_kernel(const float* __restrict__ fc_w,
                          const float* __restrict__ fc_b,
                          float* __restrict__ out) {
  int b = blockIdx.x;
  float s = g_Hf[b][threadIdx.x] * fc_w[threadIdx.x];
#pragma unroll
  for (int o = 16; o; o >>= 1) s += __shfl_xor_sync(0xFFFFFFFFu, s, o);
  __shared__ float ps[8];
  if ((threadIdx.x & 31) == 0) ps[threadIdx.x >> 5] = s;
  __syncthreads();
  if (threadIdx.x == 0) {
    float tt = 0.f;
#pragma unroll
    for (int i = 0; i < 8; i++) tt += ps[i];
    out[b] = tt + fc_b[0];
  }
}

// ---------------- launch ----------------
extern "C" void kernel_launch(void* const* d_in, const int* in_sizes, int n_in,
                              void* d_out, int out_size) {
  const float* x    = (const float*)d_in[0];
  const float* W_ih = (const float*)d_in[1];
  const float* W_hh = (const float*)d_in[2];
  const float* b_ih = (const float*)d_in[3];
  const float* b_hh = (const float*)d_in[4];
  const float* fc_w = (const float*)d_in[5];
  const float* fc_b = (const float*)d_in[6];
  float* out = (float*)d_out;

  static bool init = false;
  if (!init) {
    cudaFuncSetAttribute(lstm_kernel,
                         cudaFuncAttributeMaxDynamicSharedMemorySize, SMEM_TOTAL);
    init = true;
  }

  reset_kernel<<<1, 512>>>();
  xprep_kernel<<<65536, 256>>>(x);
  lstm_kernel<<<NBG * NGG, 256, SMEM_TOTAL>>>(W_ih, W_hh, b_ih, b_hh);
  fc_kernel<<<256, 256>>>(fc_w, fc_b, out);
}

// round 6
// speedup vs baseline: 3.4047x; 1.1140x over previous
#include <cuda_runtime.h>
#include <cuda_bf16.h>
#include <cstdint>

// ---------------- dims ----------------
#define NBG    16       // batch groups (16 batch each)
#define NGG    8        // gate-slice CTAs per group (32 h-cols each)
#define BB     16       // batch per group (MMA M)
#define T_LEN  1024
#define H_DIM  256
#define I_DIM  64
#define NKS    20       // k-steps of 16 (K = 320); ks 0..15 = h, 16..19 = x

// ---------------- smem layout (bytes) ----------------
// W fragment regions: [hi_t01, hi_t23, lo_t01, lo_t23], each [gate(4)][ks(20)][lane(32)][16B]
#define WREG     40960
#define W_OFF    0
#define HX_OFF   (4 * WREG)            // 163840: hx hi [20][32][16B] then lo (+10240)
#define SP_OFF   (HX_OFF + 20480)      // 184320: 2 k-half spills, [b(16)][136 floats]
#define SP_HALF  8704
#define SMEM_TOTAL (SP_OFF + 2 * SP_HALF)   // 201728

// ---------------- static scratch ----------------
// hx staging ring in fragment layout: [t][bg]{hi 10240 | lo 10240}
__device__ char          g_B[(size_t)(T_LEN + 1) * NBG * 20480];
__device__ float         g_Hf[256][256];   // final hidden fp32
__device__ unsigned int  g_cnt[NBG * 32];

// ---------------- helpers ----------------
__device__ __forceinline__ unsigned int ld_acq(const unsigned int* p) {
  unsigned int v;
  asm volatile("ld.acquire.gpu.global.u32 %0, [%1];" : "=r"(v) : "l"(p) : "memory");
  return v;
}
__device__ __forceinline__ void red_rel(unsigned int* p) {
  asm volatile("red.release.gpu.global.add.u32 [%0], 1;" :: "l"(p) : "memory");
}
__device__ __forceinline__ float fsig(float x) {
  x = fminf(fmaxf(x, -15.0f), 15.0f);
  return __fdividef(1.0f, 1.0f + __expf(-x));
}
__device__ __forceinline__ float ftanh(float x) {
  x = fminf(fmaxf(x, -15.0f), 15.0f);
  float e = __expf(-2.0f * x);
  return __fdividef(1.0f - e, 1.0f + e);
}
__device__ __forceinline__ void mma16816(float* d, const uint4& a,
                                         uint32_t b0, uint32_t b1) {
  asm volatile(
      "mma.sync.aligned.m16n8k16.row.col.f32.bf16.bf16.f32 "
      "{%0,%1,%2,%3}, {%4,%5,%6,%7}, {%8,%9}, {%0,%1,%2,%3};"
      : "+f"(d[0]), "+f"(d[1]), "+f"(d[2]), "+f"(d[3])
      : "r"(a.x), "r"(a.y), "r"(a.z), "r"(a.w), "r"(b0), "r"(b1));
}

// fragment address: element (batch b, k_in) within one kstep's 512B frag
__device__ __forceinline__ int hx_frag_off(int b, int k_in) {
  int u    = (k_in & 7) >> 1;
  int half = k_in & 1;
  int reg  = ((b >> 3) & 1) + ((k_in >> 3) & 1) * 2;
  return ((b & 7) * 4 + u) * 16 + reg * 4 + half * 2;
}

// ---------------- prep kernels ----------------
__global__ void reset_kernel() {
  if (threadIdx.x < NBG * 32) g_cnt[threadIdx.x] = 0u;
}

// stage x (hi/lo) into g_B k-steps 16..19 for all t
__global__ void xprep_kernel(const float* __restrict__ x) {
  int id  = blockIdx.x * 256 + threadIdx.x;      // 16,777,216
  int i   = id & 63;
  int t   = (id >> 6) & 1023;
  int bgl = id >> 16;
  float v = x[(size_t)bgl * (T_LEN * I_DIM) + t * 64 + i];
  __nv_bfloat16 hi = __float2bfloat16(v);
  __nv_bfloat16 lo = __float2bfloat16(v - __bfloat162float(hi));
  int bg = bgl >> 4, b = bgl & 15;
  int ks = 16 + (i >> 4);
  int off = ks * 512 + hx_frag_off(b, i & 15);
  char* base = g_B + ((size_t)t * NBG + bg) * 20480;
  *(__nv_bfloat16*)(base + off)         = hi;
  *(__nv_bfloat16*)(base + 10240 + off) = lo;
}

// ---------------- main persistent kernel ----------------
__global__ void __launch_bounds__(256, 1) lstm_kernel(
    const float* __restrict__ W_ih, const float* __restrict__ W_hh,
    const float* __restrict__ b_ih, const float* __restrict__ b_hh) {
  extern __shared__ char smem[];
  const int tid  = threadIdx.x;
  const int w    = tid >> 5;
  const int lane = tid & 31;
  const int bg   = blockIdx.x >> 3;
  const int gg   = blockIdx.x & 7;
  const int c0   = gg * 32;

  // ---- one-time: W slice -> smem fragment-major (hi/lo, tiles split) ----
  for (int idx = tid; idx < 128 * 320; idx += 256) {
    int r = idx / 320, k = idx - r * 320;
    int gate = r >> 5;
    int gr = gate * H_DIM + c0 + (r & 31);
    float v = (k < H_DIM) ? W_hh[gr * H_DIM + k] : W_ih[gr * I_DIM + (k - 256)];
    __nv_bfloat16 hi = __float2bfloat16(v);
    __nv_bfloat16 lo = __float2bfloat16(v - __bfloat162float(hi));
    int ks = k >> 4, k_in = k & 15;
    int u = (k_in & 7) >> 1, half = k_in & 1, rh = (k_in >> 3) & 1;
    int j = (r >> 3) & 3;
    int off = gate * 10240 + ks * 512 + ((r & 7) * 4 + u) * 16 +
              (j & 1) * 8 + rh * 4 + half * 2;
    int regidx = j >> 1;
    *(__nv_bfloat16*)(smem + W_OFF + regidx * WREG + off)       = hi;
    *(__nv_bfloat16*)(smem + W_OFF + (2 + regidx) * WREG + off) = lo;
  }

  // zero h region of hx (both planes); load x(0) frags
  for (int i = tid; i < 2048; i += 256) {   // 2048 * 16B = 32KB? no: h region = 2*8KB
    int p = i >> 10, c = i & 1023;
    if (c < 512) *(uint4*)(smem + HX_OFF + p * 10240 + c * 16) = make_uint4(0, 0, 0, 0);
  }
  const int xoff = (tid >> 7) * 10240 + 8192 + (tid & 127) * 16;
  {
    const char* src = g_B + (size_t)(0 * NBG + bg) * 20480;
    *(uint4*)(smem + HX_OFF + xoff) = __ldcg((const uint4*)(src + xoff));
  }

  // h copy-in chunk offsets (4 x 16B per thread, 16KB total)
  int hoff[4];
#pragma unroll
  for (int i = 0; i < 4; i++) {
    int q = tid + i * 256;
    hoff[i] = (q >> 9) * 10240 + (q & 511) * 16;
  }

  // ---- MMA mapping: ns = gate slice, kh = k-half (interleaved ksteps) ----
  const int ns = w & 3;
  const int kh = w >> 2;
  const char* pA_hi = smem + HX_OFF + kh * 512 + lane * 16;   // + j*1024
  const char* pA_lo = pA_hi + 10240;
  const char* pB    = smem + W_OFF + ns * 10240 + kh * 512 + lane * 16;

  // ---- epilogue mapping ----
  const int ehc = tid & 31;
  const int eb  = tid >> 5;
  float bias[4];
#pragma unroll
  for (int g = 0; g < 4; g++)
    bias[g] = b_ih[g * H_DIM + c0 + ehc] + b_hh[g * H_DIM + c0 + ehc];
  float cs[2] = {0.f, 0.f};
  const int eks = gg * 2 + (ehc >> 4);
  const int ekin = ehc & 15;

  unsigned int* flag = &g_cnt[bg * 32];
  __syncthreads();

  for (int t = 0; t < T_LEN; t++) {
    const char* ringT  = g_B + ((size_t)t * NBG + bg) * 20480;
    const char* ringT1 = g_B + ((size_t)(t + 1) * NBG + bg) * 20480;

    // ---- wait for h(t); issue h LDGs immediately after ----
    uint4 hv0, hv1, hv2, hv3;
    if (t) {
      unsigned int target = (unsigned int)(NGG * t);
      while (ld_acq(flag) < target) { }
      hv0 = __ldcg((const uint4*)(ringT + hoff[0]));
      hv1 = __ldcg((const uint4*)(ringT + hoff[1]));
      hv2 = __ldcg((const uint4*)(ringT + hoff[2]));
      hv3 = __ldcg((const uint4*)(ringT + hoff[3]));
    }
    // prefetch x(t+1) (consumed in epilogue)
    uint4 xv = __ldcg((const uint4*)(ringT1 + xoff));

    float acc[16];
#pragma unroll
    for (int i = 0; i < 16; i++) acc[i] = 0.f;

    // ---- x-part MMAs (j = 8,9 -> ksteps 16..19) while h LDGs fly ----
#pragma unroll
    for (int j = 8; j < 10; j++) {
      uint4 aH  = *(const uint4*)(pA_hi + j * 1024);
      uint4 aL  = *(const uint4*)(pA_lo + j * 1024);
      uint4 bh0 = *(const uint4*)(pB + j * 1024);
      uint4 bh1 = *(const uint4*)(pB + WREG + j * 1024);
      uint4 bl0 = *(const uint4*)(pB + 2 * WREG + j * 1024);
      uint4 bl1 = *(const uint4*)(pB + 3 * WREG + j * 1024);
      mma16816(acc + 0,  aH, bh0.x, bh0.y);
      mma16816(acc + 0,  aH, bl0.x, bl0.y);
      mma16816(acc + 0,  aL, bh0.x, bh0.y);
      mma16816(acc + 4,  aH, bh0.z, bh0.w);
      mma16816(acc + 4,  aH, bl0.z, bl0.w);
      mma16816(acc + 4,  aL, bh0.z, bh0.w);
      mma16816(acc + 8,  aH, bh1.x, bh1.y);
      mma16816(acc + 8,  aH, bl1.x, bl1.y);
      mma16816(acc + 8,  aL, bh1.x, bh1.y);
      mma16816(acc + 12, aH, bh1.z, bh1.w);
      mma16816(acc + 12, aH, bl1.z, bl1.w);
      mma16816(acc + 12, aL, bh1.z, bh1.w);
    }

    // ---- land h frags into smem ----
    if (t) {
      *(uint4*)(smem + HX_OFF + hoff[0]) = hv0;
      *(uint4*)(smem + HX_OFF + hoff[1]) = hv1;
      *(uint4*)(smem + HX_OFF + hoff[2]) = hv2;
      *(uint4*)(smem + HX_OFF + hoff[3]) = hv3;
    }
    __syncthreads();

    // ---- h-part MMAs (j = 0..7 -> ksteps 0..15) ----
#pragma unroll
    for (int j = 0; j < 8; j++) {
      uint4 aH  = *(const uint4*)(pA_hi + j * 1024);
      uint4 aL  = *(const uint4*)(pA_lo + j * 1024);
      uint4 bh0 = *(const uint4*)(pB + j * 1024);
      uint4 bh1 = *(const uint4*)(pB + WREG + j * 1024);
      uint4 bl0 = *(const uint4*)(pB + 2 * WREG + j * 1024);
      uint4 bl1 = *(const uint4*)(pB + 3 * WREG + j * 1024);
      mma16816(acc + 0,  aH, bh0.x, bh0.y);
      mma16816(acc + 0,  aH, bl0.x, bl0.y);
      mma16816(acc + 0,  aL, bh0.x, bh0.y);
      mma16816(acc + 4,  aH, bh0.z, bh0.w);
      mma16816(acc + 4,  aH, bl0.z, bl0.w);
      mma16816(acc + 4,  aL, bh0.z, bh0.w);
      mma16816(acc + 8,  aH, bh1.x, bh1.y);
      mma16816(acc + 8,  aH, bl1.x, bl1.y);
      mma16816(acc + 8,  aL, bh1.x, bh1.y);
      mma16816(acc + 12, aH, bh1.z, bh1.w);
      mma16816(acc + 12, aH, bl1.z, bl1.w);
      mma16816(acc + 12, aL, bh1.z, bh1.w);
    }

    // ---- spill partial D to smem: [kh][b][136] ----
    {
      int u = lane & 3, g = lane >> 2;
      float* sp = (float*)(smem + SP_OFF + kh * SP_HALF);
#pragma unroll
      for (int j = 0; j < 4; j++) {
        int r = ns * 32 + j * 8 + 2 * u;
        *(float2*)(sp + g * 136 + r)       = make_float2(acc[4 * j], acc[4 * j + 1]);
        *(float2*)(sp + (g + 8) * 136 + r) = make_float2(acc[4 * j + 2], acc[4 * j + 3]);
      }
    }
    __syncthreads();

    // ---- epilogue: combine halves, activations, publish h(t+1), stage x(t+1) ----
    {
      const float* s0 = (const float*)(smem + SP_OFF);
      const float* s1 = (const float*)(smem + SP_OFF + SP_HALF);
#pragma unroll
      for (int uu = 0; uu < 2; uu++) {
        int b = eb + uu * 8;
        float gi = s0[b * 136 +   0 + ehc] + s1[b * 136 +   0 + ehc] + bias[0];
        float gf = s0[b * 136 +  32 + ehc] + s1[b * 136 +  32 + ehc] + bias[1];
        float gc = s0[b * 136 +  64 + ehc] + s1[b * 136 +  64 + ehc] + bias[2];
        float go = s0[b * 136 +  96 + ehc] + s1[b * 136 +  96 + ehc] + bias[3];
        float iv = fsig(gi), fv = fsig(gf), cv = ftanh(gc), ov = fsig(go);
        float cn = fv * cs[uu] + iv * cv;
        cs[uu] = cn;
        float hv = ov * ftanh(cn);
        __nv_bfloat16 hi = __float2bfloat16(hv);
        __nv_bfloat16 lo = __float2bfloat16(hv - __bfloat162float(hi));
        int off = eks * 512 + hx_frag_off(b, ekin);
        *(__nv_bfloat16*)(ringT1 + off)         = hi;   // publish straight to ring
        *(__nv_bfloat16*)(ringT1 + 10240 + off) = lo;
        if (t == T_LEN - 1) g_Hf[bg * BB + b][c0 + ehc] = hv;
      }
      // stage x(t+1) into smem (x(t) fully consumed above)
      *(uint4*)(smem + HX_OFF + xoff) = xv;
    }
    __syncthreads();
    if (tid == 0) red_rel(flag);
  }
}

// ---------------- fc ----------------
__global__ void fc_kernel(const float* __restrict__ fc_w,
                          const float* __restrict__ fc_b,
                          float* __restrict__ out) {
  int b = blockIdx.x;
  float s = g_Hf[b][threadIdx.x] * fc_w[threadIdx.x];
#pragma unroll
  for (int o = 16; o; o >>= 1) s += __shfl_xor_sync(0xFFFFFFFFu, s, o);
  __shared__ float ps[8];
  if ((threadIdx.x & 31) == 0) ps[threadIdx.x >> 5] = s;
  __syncthreads();
  if (threadIdx.x == 0) {
    float tt = 0.f;
#pragma unroll
    for (int i = 0; i < 8; i++) tt += ps[i];
    out[b] = tt + fc_b[0];
  }
}

// ---------------- launch ----------------
extern "C" void kernel_launch(void* const* d_in, const int* in_sizes, int n_in,
                              void* d_out, int out_size) {
  const float* x    = (const float*)d_in[0];
  const float* W_ih = (const float*)d_in[1];
  const float* W_hh = (const float*)d_in[2];
  const float* b_ih = (const float*)d_in[3];
  const float* b_hh = (const float*)d_in[4];
  const float* fc_w = (const float*)d_in[5];
  const float* fc_b = (const float*)d_in[6];
  float* out = (float*)d_out;

  static bool init = false;
  if (!init) {
    cudaFuncSetAttribute(lstm_kernel,
                         cudaFuncAttributeMaxDynamicSharedMemorySize, SMEM_TOTAL);
    init = true;
  }

  reset_kernel<<<1, 512>>>();
  xprep_kernel<<<65536, 256>>>(x);
  lstm_kernel<<<NBG * NGG, 256, SMEM_TOTAL>>>(W_ih, W_hh, b_ih, b_hh);
  fc_kernel<<<256, 256>>>(fc_w, fc_b, out);
}